// round 4
// baseline (speedup 1.0000x reference)
#include <cuda_runtime.h>
#include <cstdint>

// ---------------------------------------------------------------------------
// ValueNetwork forward. Dead-code-eliminated: mlp1/global/attn branch unused.
// Live graph: self6 = state[:,0,:6]; LSTM(64 steps, in=7, hid=50) over
// state[:,:,6:13]; MLP 56->150->100->100->1.
// R2: 32-row LSTM blocks (2 CTAs/SM -> MUFU/GEMM overlap), prep kernel removed
//     (direct strided x reads, latency hidden), LDS.128 weight fetch.
// ---------------------------------------------------------------------------

#define B_SIZE 8192
#define NSTEP  64
#define ROWB   832          // floats per batch row of state (64*13)
#define HID    50
#define KDIM   57           // 7 input + 50 hidden
#define GATE   200
#define WSTR   256          // per-k weight stride (32 lanes * 8 slots, 7 used)
#define RPBL   32           // LSTM rows per block
#define RSTRL  34           // LSTM transposed smem row stride
#define RPBM   64           // MLP rows per block
#define RSTRM  66           // MLP transposed smem row stride
#define THREADS 256

typedef unsigned long long ull;

// scratch (static device array: allocation-free)
__device__ float g_hT[HID * B_SIZE];          // [u][b]: final hidden state

// ---- f32x2 helpers (sm_103a packed fp32 FMA: 2x FFMA throughput) ----------
__device__ __forceinline__ ull dup2(float v) {
    ull r;
    asm("mov.b64 %0, {%1, %1};" : "=l"(r) : "f"(v));
    return r;
}
__device__ __forceinline__ void fma2(ull& d, ull a, ull b) {
    asm("fma.rn.f32x2 %0, %1, %2, %0;" : "+l"(d) : "l"(a), "l"(b));
}
__device__ __forceinline__ float2 unpk(ull v) {
    float2 f;
    asm("mov.b64 {%0, %1}, %2;" : "=f"(f.x), "=f"(f.y) : "l"(v));
    return f;
}

__device__ __forceinline__ float sig_f(float x) {
    return __fdividef(1.f, 1.f + __expf(-x));
}
__device__ __forceinline__ float tanh_f(float x) {
    float xc = fminf(fmaxf(x, -15.f), 15.f);   // avoid exp overflow -> nan
    float e = __expf(2.f * xc);
    return __fdividef(e - 1.f, e + 1.f);
}

// ---------------------------------------------------------------------------
// LSTM: 256 blocks x 32 rows (2 CTAs/SM on 108 SMs: activation MUFU + barriers
// of one block overlap the other's GEMM). Persistent over 64 steps.
// smem: W[57][256] | bias[224] | hx[57][34] | c[50][34] | gates[200][34]
// ---------------------------------------------------------------------------
#define LSTM_SM_FLOATS (KDIM*WSTR + 224 + KDIM*RSTRL + HID*RSTRL + GATE*RSTRL)
#define LSTM_SM_BYTES  (LSTM_SM_FLOATS * 4)

__global__ __launch_bounds__(THREADS, 2) void lstm_kernel(
    const float* __restrict__ state,
    const float* __restrict__ wih, const float* __restrict__ whh,
    const float* __restrict__ bih, const float* __restrict__ bhh)
{
    extern __shared__ float sm[];
    float* Wsh  = sm;                        // 57*256
    float* bsh  = Wsh + KDIM * WSTR;         // 224
    float* hxsh = bsh + 224;                 // 57*34 (rows 0-6 x, 7-56 h)
    float* csh  = hxsh + KDIM * RSTRL;       // 50*34
    float* gsh  = csh + HID * RSTRL;         // 200*34

    const int tid = threadIdx.x;
    const int b0  = blockIdx.x * RPBL;

    // weights: gate col 7*l+j stored at slot (k, 8*l+j); slot j==7 zero pad
    for (int idx = tid; idx < KDIM * WSTR; idx += THREADS) {
        int k = idx >> 8, s = idx & 255, l = s >> 3, j = s & 7;
        int c = l * 7 + j;
        float v = 0.f;
        if (j < 7 && c < GATE)
            v = (k < 7) ? wih[k * GATE + c] : whh[(k - 7) * GATE + c];
        Wsh[idx] = v;
    }
    if (tid < 224) bsh[tid] = (tid < GATE) ? bih[tid] + bhh[tid] : 0.f;
    for (int idx = tid; idx < KDIM * RSTRL; idx += THREADS) hxsh[idx] = 0.f;
    for (int idx = tid; idx < HID * RSTRL; idx += THREADS)  csh[idx]  = 0.f;

    // x(0): 7 contiguous floats per (b, t) row -> near-coalesced gather
    const int xrow = tid / 7, xk = tid - xrow * 7;      // valid for tid<224
    const float* xptr = state + (size_t)(b0 + (tid < 224 ? xrow : 0)) * ROWB
                              + 6 + (tid < 224 ? xk : 0);
    if (tid < 224) hxsh[xk * RSTRL + xrow] = xptr[0];
    __syncthreads();

    const int lane = tid & 31;
    const int warp = tid >> 5;
    const int rb   = warp * 4;               // 8 warps * 4 rows = 32 rows
    const float* wlane = Wsh + (lane << 3);
    const float* hbase = hxsh + rb;

    ull bdup[7];
    #pragma unroll
    for (int j = 0; j < 7; ++j) bdup[j] = dup2(bsh[lane * 7 + j]);

    for (int t = 0; t < NSTEP; ++t) {
        // prefetch x(t+1): LDG latency hidden under the GEMM
        float xv = 0.f;
        {
            int t2 = (t < NSTEP - 1) ? t + 1 : t;
            if (tid < 224) xv = xptr[t2 * 13];
        }

        // gates[32][224] = hx[32][57] @ W[57][224] + bias (f32x2 row-paired)
        ull acc[2][7];
        #pragma unroll
        for (int j = 0; j < 7; ++j) { acc[0][j] = bdup[j]; acc[1][j] = bdup[j]; }

        #pragma unroll 3
        for (int k = 0; k < KDIM; ++k) {
            ull h0 = *(const ull*)(hbase + k * RSTRL);
            ull h1 = *(const ull*)(hbase + k * RSTRL + 2);
            float4 wa = *(const float4*)(wlane + (k << 8));
            float4 wb = *(const float4*)(wlane + (k << 8) + 4);
            float w[7] = {wa.x, wa.y, wa.z, wa.w, wb.x, wb.y, wb.z};
            #pragma unroll
            for (int j = 0; j < 7; ++j) {
                ull w2 = dup2(w[j]);
                fma2(acc[0][j], h0, w2);
                fma2(acc[1][j], h1, w2);
            }
        }
        #pragma unroll
        for (int j = 0; j < 7; ++j) {
            int c = lane * 7 + j;
            if (c < GATE) {
                float* gp = &gsh[c * RSTRL + rb];
                *(ull*)(gp)     = acc[0][j];
                *(ull*)(gp + 2) = acc[1][j];
            }
        }
        __syncthreads();

        // activation / state update (i,f,g,o regroup via gsh)
        for (int idx = tid; idx < HID * RPBL; idx += THREADS) {
            int r = idx & 31, u = idx >> 5;
            float gi = gsh[u * RSTRL + r];
            float gf = gsh[(HID + u) * RSTRL + r];
            float gg = gsh[(2 * HID + u) * RSTRL + r];
            float go = gsh[(3 * HID + u) * RSTRL + r];
            float c  = csh[u * RSTRL + r];
            c = sig_f(gf) * c + sig_f(gi) * tanh_f(gg);
            csh[u * RSTRL + r] = c;
            hxsh[(7 + u) * RSTRL + r] = sig_f(go) * tanh_f(c);
        }
        if (tid < 224) hxsh[xk * RSTRL + xrow] = xv;     // stage x(t+1)
        __syncthreads();
    }

    for (int idx = tid; idx < HID * RPBL; idx += THREADS) {
        int r = idx & 31, u = idx >> 5;
        g_hT[u * B_SIZE + b0 + r] = hxsh[(7 + u) * RSTRL + r];
    }
}

// ---------------------------------------------------------------------------
// MLP: all weights in smem, transposed activation buffers, f32x2 GEMMs.
// ---------------------------------------------------------------------------
template<int IN, int OUT, int LA, int CP>
__device__ __forceinline__ void mlp_layer(const float* __restrict__ Wsh,
                                          const float* __restrict__ Bsh,
                                          const float* __restrict__ Xsh,
                                          float* __restrict__ Ysh,
                                          int lane, int rb)
{
    ull acc[4][CP];
    const bool act = lane < LA;
    #pragma unroll
    for (int j = 0; j < CP; ++j) {
        ull bv = dup2(act ? Bsh[j * LA + lane] : 0.f);
        acc[0][j] = bv; acc[1][j] = bv; acc[2][j] = bv; acc[3][j] = bv;
    }
    #pragma unroll 2
    for (int k = 0; k < IN; ++k) {
        const float* xr = &Xsh[k * RSTRM + rb];
        ull h0 = *(const ull*)(xr);
        ull h1 = *(const ull*)(xr + 2);
        ull h2 = *(const ull*)(xr + 4);
        ull h3 = *(const ull*)(xr + 6);
        #pragma unroll
        for (int j = 0; j < CP; ++j) {
            ull w2 = dup2(act ? Wsh[k * OUT + j * LA + lane] : 0.f);
            fma2(acc[0][j], h0, w2);
            fma2(acc[1][j], h1, w2);
            fma2(acc[2][j], h2, w2);
            fma2(acc[3][j], h3, w2);
        }
    }
    if (act) {
        #pragma unroll
        for (int j = 0; j < CP; ++j) {
            int c = j * LA + lane;
            float* yp = &Ysh[c * RSTRM + rb];
            #pragma unroll
            for (int rp = 0; rp < 4; ++rp) {
                float2 v = unpk(acc[rp][j]);
                v.x = fmaxf(v.x, 0.f);
                v.y = fmaxf(v.y, 0.f);
                *(float2*)(yp + 2 * rp) = v;
            }
        }
    }
}

#define MLP_SM_FLOATS (8400 + 150 + 15000 + 100 + 10000 + 100 + 100 + 2 + 150*RSTRM + 150*RSTRM)
#define MLP_SM_BYTES  (MLP_SM_FLOATS * 4)

__global__ __launch_bounds__(THREADS) void mlp_kernel(
    const float* __restrict__ state,
    const float* __restrict__ w1, const float* __restrict__ b1,
    const float* __restrict__ w2, const float* __restrict__ b2,
    const float* __restrict__ w3, const float* __restrict__ b3,
    const float* __restrict__ w4, const float* __restrict__ b4,
    float* __restrict__ out)
{
    extern __shared__ float sm[];
    float* w1s = sm;                // 8400
    float* b1s = w1s + 8400;        // 150
    float* w2s = b1s + 150;         // 15000
    float* b2s = w2s + 15000;       // 100
    float* w3s = b2s + 100;         // 10000
    float* b3s = w3s + 10000;       // 100
    float* w4s = b3s + 100;         // 100
    float* b4s = w4s + 100;         // 1 (+1 pad)
    float* X   = b4s + 2;           // 150*66
    float* Y   = X + 150 * RSTRM;   // 150*66

    const int tid = threadIdx.x;
    const int b0  = blockIdx.x * RPBM;

    for (int i = tid; i < 8400; i += THREADS)  w1s[i] = w1[i];
    for (int i = tid; i < 15000; i += THREADS) w2s[i] = w2[i];
    for (int i = tid; i < 10000; i += THREADS) w3s[i] = w3[i];
    for (int i = tid; i < 150; i += THREADS)   b1s[i] = b1[i];
    for (int i = tid; i < 100; i += THREADS) {
        b2s[i] = b2[i]; b3s[i] = b3[i]; w4s[i] = w4[i];
    }
    if (tid == 0) b4s[0] = b4[0];
    // joint = [self6 | h]: self6 straight from state[:,0,:6]
    for (int idx = tid; idx < 56 * RPBM; idx += THREADS) {
        int r = idx & 63, k = idx >> 6;
        X[k * RSTRM + r] = (k < 6) ? state[(size_t)(b0 + r) * ROWB + k]
                                   : g_hT[(k - 6) * B_SIZE + b0 + r];
    }
    __syncthreads();

    const int lane = tid & 31;
    const int rb   = (tid >> 5) * 8;

    mlp_layer<56, 150, 30, 5>(w1s, b1s, X, Y, lane, rb);
    __syncthreads();
    mlp_layer<150, 100, 25, 4>(w2s, b2s, Y, X, lane, rb);
    __syncthreads();
    mlp_layer<100, 100, 25, 4>(w3s, b3s, X, Y, lane, rb);
    __syncthreads();

    if (tid < RPBM) {
        float a0 = 0.f, a1 = 0.f, a2 = 0.f, a3 = 0.f;
        #pragma unroll 5
        for (int k = 0; k < 100; k += 4) {
            a0 += Y[k * RSTRM + tid]       * w4s[k];
            a1 += Y[(k + 1) * RSTRM + tid] * w4s[k + 1];
            a2 += Y[(k + 2) * RSTRM + tid] * w4s[k + 2];
            a3 += Y[(k + 3) * RSTRM + tid] * w4s[k + 3];
        }
        out[b0 + tid] = a0 + a1 + a2 + a3 + b4s[0];
    }
}

// ---------------------------------------------------------------------------
extern "C" void kernel_launch(void* const* d_in, const int* in_sizes, int n_in,
                              void* d_out, int out_size)
{
    (void)in_sizes; (void)n_in; (void)out_size;
    const float* state = (const float*)d_in[0];
    const float* wih   = (const float*)d_in[11];
    const float* whh   = (const float*)d_in[12];
    const float* bih   = (const float*)d_in[13];
    const float* bhh   = (const float*)d_in[14];
    const float* w1    = (const float*)d_in[15];
    const float* b1    = (const float*)d_in[16];
    const float* w2    = (const float*)d_in[17];
    const float* b2    = (const float*)d_in[18];
    const float* w3    = (const float*)d_in[19];
    const float* b3    = (const float*)d_in[20];
    const float* w4    = (const float*)d_in[21];
    const float* b4    = (const float*)d_in[22];
    float* out = (float*)d_out;

    cudaFuncSetAttribute(lstm_kernel, cudaFuncAttributeMaxDynamicSharedMemorySize, LSTM_SM_BYTES);
    cudaFuncSetAttribute(mlp_kernel,  cudaFuncAttributeMaxDynamicSharedMemorySize, MLP_SM_BYTES);

    lstm_kernel<<<B_SIZE / RPBL, THREADS, LSTM_SM_BYTES>>>(state, wih, whh, bih, bhh);
    mlp_kernel<<<B_SIZE / RPBM, THREADS, MLP_SM_BYTES>>>(state, w1, b1, w2, b2,
                                                         w3, b3, w4, b4, out);
}

// round 6
// speedup vs baseline: 1.3464x; 1.3464x over previous
#include <cuda_runtime.h>
#include <cstdint>

// ---------------------------------------------------------------------------
// ValueNetwork forward. Dead-code-eliminated: mlp1/global/attn branch unused.
// Live: self6 = state[:,0,:6]; LSTM(64 steps, in=7, hid=50); MLP 56->150->100->100->1.
// R6: == R5 (warp-independent LSTM, no block barriers, c in registers,
//     warp-private hx/gates smem; despilled MLP) with the MLP smem layout
//     padded to 16B boundaries (R5's float4 STS to offset%16==8 trapped).
// ---------------------------------------------------------------------------

#define B_SIZE 8192
#define NSTEP  64
#define ROWB   832          // floats per batch row of state (64*13)
#define HID    50
#define KDIM   57           // 7 input + 50 hidden
#define GATE   200
#define WSTR   256          // per-k weight stride (32 lanes * 8 slots, 7 used)
#define THREADS 256
// LSTM per-warp regions
#define HXW_FL  (KDIM * 8)          // 456: hx[k][8 rows]
#define GW_STR  9                   // gate col stride (odd -> conflict-free STS.32)
#define GW_FL   (GATE * GW_STR)     // 1800
// MLP
#define RPBM 32
#define RSTRM 34

typedef unsigned long long ull;

__device__ float g_hT[HID * B_SIZE];          // [u][b]: final hidden state

// ---- f32x2 helpers --------------------------------------------------------
__device__ __forceinline__ ull dup2(float v) {
    ull r; asm("mov.b64 %0, {%1, %1};" : "=l"(r) : "f"(v)); return r;
}
__device__ __forceinline__ void fma2(ull& d, ull a, ull b) {
    asm("fma.rn.f32x2 %0, %1, %2, %0;" : "+l"(d) : "l"(a), "l"(b));
}
__device__ __forceinline__ float2 unpk(ull v) {
    float2 f; asm("mov.b64 {%0, %1}, %2;" : "=f"(f.x), "=f"(f.y) : "l"(v)); return f;
}
__device__ __forceinline__ float sig_f(float x) {
    return __fdividef(1.f, 1.f + __expf(-x));
}
__device__ __forceinline__ float tanh_f(float x) {
    float xc = fminf(fmaxf(x, -15.f), 15.f);
    float e = __expf(2.f * xc);
    return __fdividef(e - 1.f, e + 1.f);
}

// ---------------------------------------------------------------------------
// LSTM: 128 blocks x 64 rows; each warp owns 8 batch rows end-to-end
// (recurrence is batch-elementwise => NO inter-warp dependency, syncwarp only).
// smem: W[57][256] shared | per-warp hx[57][8] | per-warp gates[200][9]
// ---------------------------------------------------------------------------
#define LSTM_SM_FLOATS (KDIM * WSTR + 8 * (HXW_FL + GW_FL))
#define LSTM_SM_BYTES  (LSTM_SM_FLOATS * 4)

__global__ __launch_bounds__(THREADS, 1) void lstm_kernel(
    const float* __restrict__ state,
    const float* __restrict__ wih, const float* __restrict__ whh,
    const float* __restrict__ bih, const float* __restrict__ bhh)
{
    extern __shared__ float sm[];
    float* Wsh = sm;                                    // 57*256

    const int tid  = threadIdx.x;
    const int lane = tid & 31;
    const int warp = tid >> 5;

    float* hxw = sm + KDIM * WSTR + warp * HXW_FL;      // [k][8]
    float* gw  = sm + KDIM * WSTR + 8 * HXW_FL + warp * GW_FL;  // [c][9]

    // weights: gate col 7*l+j at slot (k, 8*l+j); j==7 & c>=200 zero-padded
    for (int idx = tid; idx < KDIM * WSTR; idx += THREADS) {
        int k = idx >> 8, s = idx & 255, l = s >> 3, j = s & 7;
        int c = l * 7 + j;
        float v = 0.f;
        if (j < 7 && c < GATE)
            v = (k < 7) ? wih[k * GATE + c] : whh[(k - 7) * GATE + c];
        Wsh[idx] = v;
    }

    // biases straight into registers (cols lane*7+j)
    ull bdup[7];
    #pragma unroll
    for (int j = 0; j < 7; ++j) {
        int c = lane * 7 + j;
        bdup[j] = dup2(c < GATE ? bih[c] + bhh[c] : 0.f);
    }

    // zero h rows of hx; c state lives in registers
    for (int i = lane; i < (KDIM - 7) * 8; i += 32) hxw[7 * 8 + i] = 0.f;
    float creg[13];
    #pragma unroll
    for (int i = 0; i < 13; ++i) creg[i] = 0.f;

    // x(0): warp's 8 rows x 7 dims (7 contiguous floats per (b,t) row)
    const int b0 = blockIdx.x * 64 + warp * 8;
    {
        int i0 = lane, i1 = lane + 32;
        int r0 = i0 / 7, k0 = i0 - r0 * 7;
        float x0 = state[(size_t)(b0 + r0) * ROWB + 6 + k0];
        float x1 = 0.f;
        int r1 = i1 / 7, k1 = i1 - r1 * 7;
        if (i1 < 56) x1 = state[(size_t)(b0 + r1) * ROWB + 6 + k1];
        hxw[k0 * 8 + r0] = x0;
        if (i1 < 56) hxw[k1 * 8 + r1] = x1;
    }
    __syncthreads();    // Wsh ready (only block-wide sync in the kernel)

    const float* wl = Wsh + (lane << 3);
    // x gather coords (fixed per lane)
    const int i1ok = (lane + 32) < 56;
    const int xr0 = lane / 7,        xk0 = lane - xr0 * 7;
    const int xr1 = (lane + 32) / 7, xk1 = (lane + 32) - xr1 * 7;
    const float* xp0 = state + (size_t)(b0 + xr0) * ROWB + 6 + xk0;
    const float* xp1 = state + (size_t)(b0 + (i1ok ? xr1 : 0)) * ROWB + 6 + xk1;

    for (int t = 0; t < NSTEP; ++t) {
        // prefetch x(t+1): LDG latency hidden under the GEMM
        int t2 = (t < NSTEP - 1) ? t + 1 : t;
        float xv0 = xp0[t2 * 13];
        float xv1 = i1ok ? xp1[t2 * 13] : 0.f;

        // gates[8 rows][224 cols] = hx[8][57] @ W[57][224] + b
        ull acc[4][7];
        #pragma unroll
        for (int j = 0; j < 7; ++j) {
            acc[0][j] = bdup[j]; acc[1][j] = bdup[j];
            acc[2][j] = bdup[j]; acc[3][j] = bdup[j];
        }
        #pragma unroll 3
        for (int k = 0; k < KDIM; ++k) {
            const float* hb = hxw + k * 8;
            ull h0 = *(const ull*)(hb);
            ull h1 = *(const ull*)(hb + 2);
            ull h2 = *(const ull*)(hb + 4);
            ull h3 = *(const ull*)(hb + 6);
            float4 wa = *(const float4*)(wl + (k << 8));
            float4 wb = *(const float4*)(wl + (k << 8) + 4);
            float w[7] = {wa.x, wa.y, wa.z, wa.w, wb.x, wb.y, wb.z};
            #pragma unroll
            for (int j = 0; j < 7; ++j) {
                ull w2 = dup2(w[j]);
                fma2(acc[0][j], h0, w2);
                fma2(acc[1][j], h1, w2);
                fma2(acc[2][j], h2, w2);
                fma2(acc[3][j], h3, w2);
            }
        }
        // spill gates to warp-private smem (stride 9 -> conflict-free)
        #pragma unroll
        for (int j = 0; j < 7; ++j) {
            int c = lane * 7 + j;
            if (c < GATE) {
                float* gp = gw + c * GW_STR;
                #pragma unroll
                for (int p = 0; p < 4; ++p) {
                    float2 v = unpk(acc[p][j]);
                    gp[2 * p] = v.x; gp[2 * p + 1] = v.y;
                }
            }
        }
        __syncwarp();   // gate stores & hx reads done

        // x(t+1) into hx rows 0..6
        hxw[xk0 * 8 + xr0] = xv0;
        if (i1ok) hxw[xk1 * 8 + xr1] = xv1;

        // activation: 50 units x 8 rows, c in regs, h -> hx
        #pragma unroll
        for (int i = 0; i < 13; ++i) {
            int idx = lane + 32 * i;
            if (idx < HID * 8) {
                int u = idx >> 3, r = idx & 7;
                float gi = gw[u * GW_STR + r];
                float gf = gw[(HID + u) * GW_STR + r];
                float gg = gw[(2 * HID + u) * GW_STR + r];
                float go = gw[(3 * HID + u) * GW_STR + r];
                float c = sig_f(gf) * creg[i] + sig_f(gi) * tanh_f(gg);
                creg[i] = c;
                hxw[(7 + u) * 8 + r] = sig_f(go) * tanh_f(c);
            }
        }
        __syncwarp();   // h/x visible before next GEMM
    }

    // final h -> global [u][b]
    #pragma unroll
    for (int i = 0; i < 13; ++i) {
        int idx = lane + 32 * i;
        if (idx < HID * 8) {
            int u = idx >> 3, r = idx & 7;
            g_hT[u * B_SIZE + b0 + r] = hxw[(7 + u) * 8 + r];
        }
    }
}

// ---------------------------------------------------------------------------
// MLP: 32 rows/block, grid 256; acc[2][CP] (no spills); weights in smem.
// All smem regions padded to 16B (float4 staging requires it).
// ---------------------------------------------------------------------------
template<int IN, int OUT, int LA, int CP>
__device__ __forceinline__ void mlp_layer(const float* __restrict__ Wsh,
                                          const float* __restrict__ Bsh,
                                          const float* __restrict__ Xsh,
                                          float* __restrict__ Ysh,
                                          int lane, int rb)
{
    ull acc[2][CP];
    const bool act = lane < LA;
    #pragma unroll
    for (int j = 0; j < CP; ++j) {
        ull bv = dup2(act ? Bsh[j * LA + lane] : 0.f);
        acc[0][j] = bv; acc[1][j] = bv;
    }
    #pragma unroll 2
    for (int k = 0; k < IN; ++k) {
        const float* xr = &Xsh[k * RSTRM + rb];
        ull h0 = *(const ull*)(xr);
        ull h1 = *(const ull*)(xr + 2);
        #pragma unroll
        for (int j = 0; j < CP; ++j) {
            ull w2 = dup2(act ? Wsh[k * OUT + j * LA + lane] : 0.f);
            fma2(acc[0][j], h0, w2);
            fma2(acc[1][j], h1, w2);
        }
    }
    if (act) {
        #pragma unroll
        for (int j = 0; j < CP; ++j) {
            int c = j * LA + lane;
            float* yp = &Ysh[c * RSTRM + rb];
            #pragma unroll
            for (int rp = 0; rp < 2; ++rp) {
                float2 v = unpk(acc[rp][j]);
                v.x = fmaxf(v.x, 0.f);
                v.y = fmaxf(v.y, 0.f);
                *(float2*)(yp + 2 * rp) = v;
            }
        }
    }
}

// 16B-aligned smem layout (all offsets multiples of 4 floats)
#define OFF_W1 0
#define OFF_B1 8400
#define OFF_W2 8552            // 8400 + 152
#define OFF_B2 23552           // + 15000
#define OFF_W3 23656           // + 104
#define OFF_B3 33656           // + 10000
#define OFF_W4 33760           // + 104
#define OFF_B4 33864           // + 104
#define OFF_X  33868           // + 4
#define OFF_Y  (OFF_X + 150 * RSTRM)
#define MLP_SM_FLOATS (OFF_Y + 150 * RSTRM)
#define MLP_SM_BYTES  (MLP_SM_FLOATS * 4)

__global__ __launch_bounds__(THREADS, 1) void mlp_kernel(
    const float* __restrict__ state,
    const float* __restrict__ w1, const float* __restrict__ b1,
    const float* __restrict__ w2, const float* __restrict__ b2,
    const float* __restrict__ w3, const float* __restrict__ b3,
    const float* __restrict__ w4, const float* __restrict__ b4,
    float* __restrict__ out)
{
    extern __shared__ float sm[];
    float* w1s = sm + OFF_W1;
    float* b1s = sm + OFF_B1;
    float* w2s = sm + OFF_W2;
    float* b2s = sm + OFF_B2;
    float* w3s = sm + OFF_W3;
    float* b3s = sm + OFF_B3;
    float* w4s = sm + OFF_W4;
    float* b4s = sm + OFF_B4;
    float* X   = sm + OFF_X;
    float* Y   = sm + OFF_Y;

    const int tid = threadIdx.x;
    const int b0  = blockIdx.x * RPBM;

    // vectorized weight loads (all dst offsets 16B-aligned)
    for (int i = tid; i < 2100; i += THREADS)
        ((float4*)w1s)[i] = ((const float4*)w1)[i];
    for (int i = tid; i < 3750; i += THREADS)
        ((float4*)w2s)[i] = ((const float4*)w2)[i];
    for (int i = tid; i < 2500; i += THREADS)
        ((float4*)w3s)[i] = ((const float4*)w3)[i];
    if (tid < 150) b1s[tid] = b1[tid];
    if (tid < 100) { b2s[tid] = b2[tid]; b3s[tid] = b3[tid]; w4s[tid] = w4[tid]; }
    if (tid == 0) b4s[0] = b4[0];
    // joint = [self6 | h]
    for (int idx = tid; idx < 56 * RPBM; idx += THREADS) {
        int r = idx & 31, k = idx >> 5;
        X[k * RSTRM + r] = (k < 6) ? state[(size_t)(b0 + r) * ROWB + k]
                                   : g_hT[(k - 6) * B_SIZE + b0 + r];
    }
    __syncthreads();

    const int lane = tid & 31;
    const int rb   = (tid >> 5) * 4;

    mlp_layer<56, 150, 30, 5>(w1s, b1s, X, Y, lane, rb);
    __syncthreads();
    mlp_layer<150, 100, 25, 4>(w2s, b2s, Y, X, lane, rb);
    __syncthreads();
    mlp_layer<100, 100, 25, 4>(w3s, b3s, X, Y, lane, rb);
    __syncthreads();

    if (tid < RPBM) {
        float a0 = 0.f, a1 = 0.f, a2 = 0.f, a3 = 0.f;
        #pragma unroll 5
        for (int k = 0; k < 100; k += 4) {
            a0 += Y[k * RSTRM + tid]       * w4s[k];
            a1 += Y[(k + 1) * RSTRM + tid] * w4s[k + 1];
            a2 += Y[(k + 2) * RSTRM + tid] * w4s[k + 2];
            a3 += Y[(k + 3) * RSTRM + tid] * w4s[k + 3];
        }
        out[b0 + tid] = a0 + a1 + a2 + a3 + b4s[0];
    }
}

// ---------------------------------------------------------------------------
extern "C" void kernel_launch(void* const* d_in, const int* in_sizes, int n_in,
                              void* d_out, int out_size)
{
    (void)in_sizes; (void)n_in; (void)out_size;
    const float* state = (const float*)d_in[0];
    const float* wih   = (const float*)d_in[11];
    const float* whh   = (const float*)d_in[12];
    const float* bih   = (const float*)d_in[13];
    const float* bhh   = (const float*)d_in[14];
    const float* w1    = (const float*)d_in[15];
    const float* b1    = (const float*)d_in[16];
    const float* w2    = (const float*)d_in[17];
    const float* b2    = (const float*)d_in[18];
    const float* w3    = (const float*)d_in[19];
    const float* b3    = (const float*)d_in[20];
    const float* w4    = (const float*)d_in[21];
    const float* b4    = (const float*)d_in[22];
    float* out = (float*)d_out;

    cudaFuncSetAttribute(lstm_kernel, cudaFuncAttributeMaxDynamicSharedMemorySize, LSTM_SM_BYTES);
    cudaFuncSetAttribute(mlp_kernel,  cudaFuncAttributeMaxDynamicSharedMemorySize, MLP_SM_BYTES);

    lstm_kernel<<<B_SIZE / 64, THREADS, LSTM_SM_BYTES>>>(state, wih, whh, bih, bhh);
    mlp_kernel<<<B_SIZE / RPBM, THREADS, MLP_SM_BYTES>>>(state, w1, b1, w2, b2,
                                                         w3, b3, w4, b4, out);
}

// round 7
// speedup vs baseline: 1.3477x; 1.0010x over previous
#include <cuda_runtime.h>
#include <cstdint>

// ---------------------------------------------------------------------------
// ValueNetwork forward. Dead-code-eliminated: mlp1/global/attn branch unused.
// Live: self6 = state[:,0,:6]; LSTM(64 steps, in=7, hid=50); MLP 56->150->100->100->1.
// R7: LSTM warp anti-phasing (warps 4-7 delayed ~2.5k cyc so each SMSP's two
//     warps alternate GEMM/MUFU phases -> FMA pipe never idles);
//     MLP grid 128 x two 32-row passes (weights staged once per block).
// ---------------------------------------------------------------------------

#define B_SIZE 8192
#define NSTEP  64
#define ROWB   832          // floats per batch row of state (64*13)
#define HID    50
#define KDIM   57           // 7 input + 50 hidden
#define GATE   200
#define WSTR   256          // per-k weight stride (32 lanes * 8 slots, 7 used)
#define THREADS 256
// LSTM per-warp regions
#define HXW_FL  (KDIM * 8)          // 456: hx[k][8 rows]
#define GW_STR  9                   // gate col stride (odd -> conflict-free STS.32)
#define GW_FL   (GATE * GW_STR)     // 1800
// MLP
#define RPBM 32
#define RSTRM 34

typedef unsigned long long ull;

__device__ float g_hT[HID * B_SIZE];          // [u][b]: final hidden state

// ---- f32x2 helpers --------------------------------------------------------
__device__ __forceinline__ ull dup2(float v) {
    ull r; asm("mov.b64 %0, {%1, %1};" : "=l"(r) : "f"(v)); return r;
}
__device__ __forceinline__ void fma2(ull& d, ull a, ull b) {
    asm("fma.rn.f32x2 %0, %1, %2, %0;" : "+l"(d) : "l"(a), "l"(b));
}
__device__ __forceinline__ float2 unpk(ull v) {
    float2 f; asm("mov.b64 {%0, %1}, %2;" : "=f"(f.x), "=f"(f.y) : "l"(v)); return f;
}
__device__ __forceinline__ float sig_f(float x) {
    return __fdividef(1.f, 1.f + __expf(-x));
}
__device__ __forceinline__ float tanh_f(float x) {
    float xc = fminf(fmaxf(x, -15.f), 15.f);
    float e = __expf(2.f * xc);
    return __fdividef(e - 1.f, e + 1.f);
}

// ---------------------------------------------------------------------------
// LSTM: 128 blocks x 64 rows; each warp owns 8 batch rows end-to-end
// (recurrence is batch-elementwise => NO inter-warp dependency, syncwarp only).
// smem: W[57][256] shared | per-warp hx[57][8] | per-warp gates[200][9]
// ---------------------------------------------------------------------------
#define LSTM_SM_FLOATS (KDIM * WSTR + 8 * (HXW_FL + GW_FL))
#define LSTM_SM_BYTES  (LSTM_SM_FLOATS * 4)

__global__ __launch_bounds__(THREADS, 1) void lstm_kernel(
    const float* __restrict__ state,
    const float* __restrict__ wih, const float* __restrict__ whh,
    const float* __restrict__ bih, const float* __restrict__ bhh)
{
    extern __shared__ float sm[];
    float* Wsh = sm;                                    // 57*256

    const int tid  = threadIdx.x;
    const int lane = tid & 31;
    const int warp = tid >> 5;

    float* hxw = sm + KDIM * WSTR + warp * HXW_FL;      // [k][8]
    float* gw  = sm + KDIM * WSTR + 8 * HXW_FL + warp * GW_FL;  // [c][9]

    // weights: gate col 7*l+j at slot (k, 8*l+j); j==7 & c>=200 zero-padded
    for (int idx = tid; idx < KDIM * WSTR; idx += THREADS) {
        int k = idx >> 8, s = idx & 255, l = s >> 3, j = s & 7;
        int c = l * 7 + j;
        float v = 0.f;
        if (j < 7 && c < GATE)
            v = (k < 7) ? wih[k * GATE + c] : whh[(k - 7) * GATE + c];
        Wsh[idx] = v;
    }

    // biases straight into registers (cols lane*7+j)
    ull bdup[7];
    #pragma unroll
    for (int j = 0; j < 7; ++j) {
        int c = lane * 7 + j;
        bdup[j] = dup2(c < GATE ? bih[c] + bhh[c] : 0.f);
    }

    // zero h rows of hx; c state lives in registers
    for (int i = lane; i < (KDIM - 7) * 8; i += 32) hxw[7 * 8 + i] = 0.f;
    float creg[13];
    #pragma unroll
    for (int i = 0; i < 13; ++i) creg[i] = 0.f;

    // x(0): warp's 8 rows x 7 dims (7 contiguous floats per (b,t) row)
    const int b0 = blockIdx.x * 64 + warp * 8;
    {
        int i0 = lane, i1 = lane + 32;
        int r0 = i0 / 7, k0 = i0 - r0 * 7;
        float x0 = state[(size_t)(b0 + r0) * ROWB + 6 + k0];
        float x1 = 0.f;
        int r1 = i1 / 7, k1 = i1 - r1 * 7;
        if (i1 < 56) x1 = state[(size_t)(b0 + r1) * ROWB + 6 + k1];
        hxw[k0 * 8 + r0] = x0;
        if (i1 < 56) hxw[k1 * 8 + r1] = x1;
    }
    __syncthreads();    // Wsh ready (only block-wide sync in the kernel)

    // ---- anti-phase stagger: the second warp on each SMSP (warps 4-7)
    // burns ~2560 cyc in a dependent FMA chain so the two warps sharing an
    // SMSP alternate GEMM (FMA-pipe) and activation (MUFU) phases.
    if (warp >= 4) {
        float d = (float)lane + 1.0f;
        #pragma unroll 1
        for (int i = 0; i < 640; ++i)
            d = fmaf(d, 0.9999999f, 1e-7f);     // 4-cyc RAW chain, discarded
        gw[0] = d;                               // keep live (overwritten at t=0)
    }

    const float* wl = Wsh + (lane << 3);
    // x gather coords (fixed per lane)
    const int i1ok = (lane + 32) < 56;
    const int xr0 = lane / 7,        xk0 = lane - xr0 * 7;
    const int xr1 = (lane + 32) / 7, xk1 = (lane + 32) - xr1 * 7;
    const float* xp0 = state + (size_t)(b0 + xr0) * ROWB + 6 + xk0;
    const float* xp1 = state + (size_t)(b0 + (i1ok ? xr1 : 0)) * ROWB + 6 + xk1;

    for (int t = 0; t < NSTEP; ++t) {
        // prefetch x(t+1): LDG latency hidden under the GEMM
        int t2 = (t < NSTEP - 1) ? t + 1 : t;
        float xv0 = xp0[t2 * 13];
        float xv1 = i1ok ? xp1[t2 * 13] : 0.f;

        // gates[8 rows][224 cols] = hx[8][57] @ W[57][224] + b
        ull acc[4][7];
        #pragma unroll
        for (int j = 0; j < 7; ++j) {
            acc[0][j] = bdup[j]; acc[1][j] = bdup[j];
            acc[2][j] = bdup[j]; acc[3][j] = bdup[j];
        }
        #pragma unroll 3
        for (int k = 0; k < KDIM; ++k) {
            const float* hb = hxw + k * 8;
            ull h0 = *(const ull*)(hb);
            ull h1 = *(const ull*)(hb + 2);
            ull h2 = *(const ull*)(hb + 4);
            ull h3 = *(const ull*)(hb + 6);
            float4 wa = *(const float4*)(wl + (k << 8));
            float4 wb = *(const float4*)(wl + (k << 8) + 4);
            float w[7] = {wa.x, wa.y, wa.z, wa.w, wb.x, wb.y, wb.z};
            #pragma unroll
            for (int j = 0; j < 7; ++j) {
                ull w2 = dup2(w[j]);
                fma2(acc[0][j], h0, w2);
                fma2(acc[1][j], h1, w2);
                fma2(acc[2][j], h2, w2);
                fma2(acc[3][j], h3, w2);
            }
        }
        // spill gates to warp-private smem (stride 9 -> conflict-free)
        #pragma unroll
        for (int j = 0; j < 7; ++j) {
            int c = lane * 7 + j;
            if (c < GATE) {
                float* gp = gw + c * GW_STR;
                #pragma unroll
                for (int p = 0; p < 4; ++p) {
                    float2 v = unpk(acc[p][j]);
                    gp[2 * p] = v.x; gp[2 * p + 1] = v.y;
                }
            }
        }
        __syncwarp();   // gate stores & hx reads done

        // x(t+1) into hx rows 0..6
        hxw[xk0 * 8 + xr0] = xv0;
        if (i1ok) hxw[xk1 * 8 + xr1] = xv1;

        // activation: 50 units x 8 rows, c in regs, h -> hx
        #pragma unroll
        for (int i = 0; i < 13; ++i) {
            int idx = lane + 32 * i;
            if (idx < HID * 8) {
                int u = idx >> 3, r = idx & 7;
                float gi = gw[u * GW_STR + r];
                float gf = gw[(HID + u) * GW_STR + r];
                float gg = gw[(2 * HID + u) * GW_STR + r];
                float go = gw[(3 * HID + u) * GW_STR + r];
                float c = sig_f(gf) * creg[i] + sig_f(gi) * tanh_f(gg);
                creg[i] = c;
                hxw[(7 + u) * 8 + r] = sig_f(go) * tanh_f(c);
            }
        }
        __syncwarp();   // h/x visible before next GEMM
    }

    // final h -> global [u][b]
    #pragma unroll
    for (int i = 0; i < 13; ++i) {
        int idx = lane + 32 * i;
        if (idx < HID * 8) {
            int u = idx >> 3, r = idx & 7;
            g_hT[u * B_SIZE + b0 + r] = hxw[(7 + u) * 8 + r];
        }
    }
}

// ---------------------------------------------------------------------------
// MLP: grid 128, 64 rows/block in two 32-row passes; weights staged once.
// acc[2][CP] (no spills). All smem regions 16B-aligned.
// ---------------------------------------------------------------------------
template<int IN, int OUT, int LA, int CP>
__device__ __forceinline__ void mlp_layer(const float* __restrict__ Wsh,
                                          const float* __restrict__ Bsh,
                                          const float* __restrict__ Xsh,
                                          float* __restrict__ Ysh,
                                          int lane, int rb)
{
    ull acc[2][CP];
    const bool act = lane < LA;
    #pragma unroll
    for (int j = 0; j < CP; ++j) {
        ull bv = dup2(act ? Bsh[j * LA + lane] : 0.f);
        acc[0][j] = bv; acc[1][j] = bv;
    }
    #pragma unroll 2
    for (int k = 0; k < IN; ++k) {
        const float* xr = &Xsh[k * RSTRM + rb];
        ull h0 = *(const ull*)(xr);
        ull h1 = *(const ull*)(xr + 2);
        #pragma unroll
        for (int j = 0; j < CP; ++j) {
            ull w2 = dup2(act ? Wsh[k * OUT + j * LA + lane] : 0.f);
            fma2(acc[0][j], h0, w2);
            fma2(acc[1][j], h1, w2);
        }
    }
    if (act) {
        #pragma unroll
        for (int j = 0; j < CP; ++j) {
            int c = j * LA + lane;
            float* yp = &Ysh[c * RSTRM + rb];
            #pragma unroll
            for (int rp = 0; rp < 2; ++rp) {
                float2 v = unpk(acc[rp][j]);
                v.x = fmaxf(v.x, 0.f);
                v.y = fmaxf(v.y, 0.f);
                *(float2*)(yp + 2 * rp) = v;
            }
        }
    }
}

// 16B-aligned smem layout (all offsets multiples of 4 floats)
#define OFF_W1 0
#define OFF_B1 8400
#define OFF_W2 8552            // 8400 + 152
#define OFF_B2 23552           // + 15000
#define OFF_W3 23656           // + 104
#define OFF_B3 33656           // + 10000
#define OFF_W4 33760           // + 104
#define OFF_B4 33864           // + 104
#define OFF_X  33868           // + 4
#define OFF_Y  (OFF_X + 150 * RSTRM)
#define MLP_SM_FLOATS (OFF_Y + 150 * RSTRM)
#define MLP_SM_BYTES  (MLP_SM_FLOATS * 4)

__global__ __launch_bounds__(THREADS, 1) void mlp_kernel(
    const float* __restrict__ state,
    const float* __restrict__ w1, const float* __restrict__ b1,
    const float* __restrict__ w2, const float* __restrict__ b2,
    const float* __restrict__ w3, const float* __restrict__ b3,
    const float* __restrict__ w4, const float* __restrict__ b4,
    float* __restrict__ out)
{
    extern __shared__ float sm[];
    float* w1s = sm + OFF_W1;
    float* b1s = sm + OFF_B1;
    float* w2s = sm + OFF_W2;
    float* b2s = sm + OFF_B2;
    float* w3s = sm + OFF_W3;
    float* b3s = sm + OFF_B3;
    float* w4s = sm + OFF_W4;
    float* b4s = sm + OFF_B4;
    float* X   = sm + OFF_X;
    float* Y   = sm + OFF_Y;

    const int tid = threadIdx.x;

    // vectorized weight loads (all dst offsets 16B-aligned), once per block
    for (int i = tid; i < 2100; i += THREADS)
        ((float4*)w1s)[i] = ((const float4*)w1)[i];
    for (int i = tid; i < 3750; i += THREADS)
        ((float4*)w2s)[i] = ((const float4*)w2)[i];
    for (int i = tid; i < 2500; i += THREADS)
        ((float4*)w3s)[i] = ((const float4*)w3)[i];
    if (tid < 150) b1s[tid] = b1[tid];
    if (tid < 100) { b2s[tid] = b2[tid]; b3s[tid] = b3[tid]; w4s[tid] = w4[tid]; }
    if (tid == 0) b4s[0] = b4[0];

    const int lane = tid & 31;
    const int rb   = (tid >> 5) * 4;

    #pragma unroll 1
    for (int pass = 0; pass < 2; ++pass) {
        const int b0 = blockIdx.x * 64 + pass * RPBM;
        __syncthreads();    // weights ready (pass 0) / prev pass done reading
        // joint = [self6 | h]
        for (int idx = tid; idx < 56 * RPBM; idx += THREADS) {
            int r = idx & 31, k = idx >> 5;
            X[k * RSTRM + r] = (k < 6) ? state[(size_t)(b0 + r) * ROWB + k]
                                       : g_hT[(k - 6) * B_SIZE + b0 + r];
        }
        __syncthreads();

        mlp_layer<56, 150, 30, 5>(w1s, b1s, X, Y, lane, rb);
        __syncthreads();
        mlp_layer<150, 100, 25, 4>(w2s, b2s, Y, X, lane, rb);
        __syncthreads();
        mlp_layer<100, 100, 25, 4>(w3s, b3s, X, Y, lane, rb);
        __syncthreads();

        if (tid < RPBM) {
            float a0 = 0.f, a1 = 0.f, a2 = 0.f, a3 = 0.f;
            #pragma unroll 5
            for (int k = 0; k < 100; k += 4) {
                a0 += Y[k * RSTRM + tid]       * w4s[k];
                a1 += Y[(k + 1) * RSTRM + tid] * w4s[k + 1];
                a2 += Y[(k + 2) * RSTRM + tid] * w4s[k + 2];
                a3 += Y[(k + 3) * RSTRM + tid] * w4s[k + 3];
            }
            out[b0 + tid] = a0 + a1 + a2 + a3 + b4s[0];
        }
    }
}

// ---------------------------------------------------------------------------
extern "C" void kernel_launch(void* const* d_in, const int* in_sizes, int n_in,
                              void* d_out, int out_size)
{
    (void)in_sizes; (void)n_in; (void)out_size;
    const float* state = (const float*)d_in[0];
    const float* wih   = (const float*)d_in[11];
    const float* whh   = (const float*)d_in[12];
    const float* bih   = (const float*)d_in[13];
    const float* bhh   = (const float*)d_in[14];
    const float* w1    = (const float*)d_in[15];
    const float* b1    = (const float*)d_in[16];
    const float* w2    = (const float*)d_in[17];
    const float* b2    = (const float*)d_in[18];
    const float* w3    = (const float*)d_in[19];
    const float* b3    = (const float*)d_in[20];
    const float* w4    = (const float*)d_in[21];
    const float* b4    = (const float*)d_in[22];
    float* out = (float*)d_out;

    cudaFuncSetAttribute(lstm_kernel, cudaFuncAttributeMaxDynamicSharedMemorySize, LSTM_SM_BYTES);
    cudaFuncSetAttribute(mlp_kernel,  cudaFuncAttributeMaxDynamicSharedMemorySize, MLP_SM_BYTES);

    lstm_kernel<<<B_SIZE / 64, THREADS, LSTM_SM_BYTES>>>(state, wih, whh, bih, bhh);
    mlp_kernel<<<B_SIZE / 64, THREADS, MLP_SM_BYTES>>>(state, w1, b1, w2, b2,
                                                       w3, b3, w4, b4, out);
}

// round 8
// speedup vs baseline: 1.5321x; 1.1368x over previous
#include <cuda_runtime.h>
#include <cstdint>

// ---------------------------------------------------------------------------
// ValueNetwork forward. Dead-code-eliminated: mlp1/global/attn branch unused.
// Live: self6 = state[:,0,:6]; LSTM(64 steps, in=7, hid=50); MLP 56->150->100->100->1.
// R8: MUFU.TANH activations (tanh.approx: 5 MUFU/unit instead of 10, 3x
//     shorter chains); stagger removed (arbiter erases it); MLP 512 threads
//     (4 warps/SMSP for latency hiding), one 64-row pass.
// ---------------------------------------------------------------------------

#define B_SIZE 8192
#define NSTEP  64
#define ROWB   832          // floats per batch row of state (64*13)
#define HID    50
#define KDIM   57           // 7 input + 50 hidden
#define GATE   200
#define WSTR   256          // per-k weight stride (32 lanes * 8 slots, 7 used)
#define THREADS 256
// LSTM per-warp regions
#define HXW_FL  (KDIM * 8)          // 456: hx[k][8 rows]
#define GW_STR  9                   // gate col stride (odd -> conflict-free STS.32)
#define GW_FL   (GATE * GW_STR)     // 1800
// MLP
#define TMLP   512
#define RPBM   64
#define RSTRM  66

typedef unsigned long long ull;

__device__ float g_hT[HID * B_SIZE];          // [u][b]: final hidden state

// ---- f32x2 helpers --------------------------------------------------------
__device__ __forceinline__ ull dup2(float v) {
    ull r; asm("mov.b64 %0, {%1, %1};" : "=l"(r) : "f"(v)); return r;
}
__device__ __forceinline__ void fma2(ull& d, ull a, ull b) {
    asm("fma.rn.f32x2 %0, %1, %2, %0;" : "+l"(d) : "l"(a), "l"(b));
}
__device__ __forceinline__ float2 unpk(ull v) {
    float2 f; asm("mov.b64 {%0, %1}, %2;" : "=f"(f.x), "=f"(f.y) : "l"(v)); return f;
}
// ---- MUFU.TANH activations -------------------------------------------------
__device__ __forceinline__ float tanh_a(float x) {
    float y; asm("tanh.approx.f32 %0, %1;" : "=f"(y) : "f"(x)); return y;
}
__device__ __forceinline__ float sig_a(float x) {      // 0.5*tanh(x/2)+0.5
    return fmaf(tanh_a(0.5f * x), 0.5f, 0.5f);
}

// ---------------------------------------------------------------------------
// LSTM: 128 blocks x 64 rows; each warp owns 8 batch rows end-to-end
// (recurrence is batch-elementwise => NO inter-warp dependency, syncwarp only).
// smem: W[57][256] shared | per-warp hx[57][8] | per-warp gates[200][9]
// ---------------------------------------------------------------------------
#define LSTM_SM_FLOATS (KDIM * WSTR + 8 * (HXW_FL + GW_FL))
#define LSTM_SM_BYTES  (LSTM_SM_FLOATS * 4)

__global__ __launch_bounds__(THREADS, 1) void lstm_kernel(
    const float* __restrict__ state,
    const float* __restrict__ wih, const float* __restrict__ whh,
    const float* __restrict__ bih, const float* __restrict__ bhh)
{
    extern __shared__ float sm[];
    float* Wsh = sm;                                    // 57*256

    const int tid  = threadIdx.x;
    const int lane = tid & 31;
    const int warp = tid >> 5;

    float* hxw = sm + KDIM * WSTR + warp * HXW_FL;      // [k][8]
    float* gw  = sm + KDIM * WSTR + 8 * HXW_FL + warp * GW_FL;  // [c][9]

    // weights: gate col 7*l+j at slot (k, 8*l+j); j==7 & c>=200 zero-padded
    for (int idx = tid; idx < KDIM * WSTR; idx += THREADS) {
        int k = idx >> 8, s = idx & 255, l = s >> 3, j = s & 7;
        int c = l * 7 + j;
        float v = 0.f;
        if (j < 7 && c < GATE)
            v = (k < 7) ? wih[k * GATE + c] : whh[(k - 7) * GATE + c];
        Wsh[idx] = v;
    }

    // biases straight into registers (cols lane*7+j)
    ull bdup[7];
    #pragma unroll
    for (int j = 0; j < 7; ++j) {
        int c = lane * 7 + j;
        bdup[j] = dup2(c < GATE ? bih[c] + bhh[c] : 0.f);
    }

    // zero h rows of hx; c state lives in registers
    for (int i = lane; i < (KDIM - 7) * 8; i += 32) hxw[7 * 8 + i] = 0.f;
    float creg[13];
    #pragma unroll
    for (int i = 0; i < 13; ++i) creg[i] = 0.f;

    // x(0): warp's 8 rows x 7 dims (7 contiguous floats per (b,t) row)
    const int b0 = blockIdx.x * 64 + warp * 8;
    {
        int i0 = lane, i1 = lane + 32;
        int r0 = i0 / 7, k0 = i0 - r0 * 7;
        float x0 = state[(size_t)(b0 + r0) * ROWB + 6 + k0];
        float x1 = 0.f;
        int r1 = i1 / 7, k1 = i1 - r1 * 7;
        if (i1 < 56) x1 = state[(size_t)(b0 + r1) * ROWB + 6 + k1];
        hxw[k0 * 8 + r0] = x0;
        if (i1 < 56) hxw[k1 * 8 + r1] = x1;
    }
    __syncthreads();    // Wsh ready (only block-wide sync in the kernel)

    const float* wl = Wsh + (lane << 3);
    // x gather coords (fixed per lane)
    const int i1ok = (lane + 32) < 56;
    const int xr0 = lane / 7,        xk0 = lane - xr0 * 7;
    const int xr1 = (lane + 32) / 7, xk1 = (lane + 32) - xr1 * 7;
    const float* xp0 = state + (size_t)(b0 + xr0) * ROWB + 6 + xk0;
    const float* xp1 = state + (size_t)(b0 + (i1ok ? xr1 : 0)) * ROWB + 6 + xk1;

    for (int t = 0; t < NSTEP; ++t) {
        // prefetch x(t+1): LDG latency hidden under the GEMM
        int t2 = (t < NSTEP - 1) ? t + 1 : t;
        float xv0 = xp0[t2 * 13];
        float xv1 = i1ok ? xp1[t2 * 13] : 0.f;

        // gates[8 rows][224 cols] = hx[8][57] @ W[57][224] + b
        ull acc[4][7];
        #pragma unroll
        for (int j = 0; j < 7; ++j) {
            acc[0][j] = bdup[j]; acc[1][j] = bdup[j];
            acc[2][j] = bdup[j]; acc[3][j] = bdup[j];
        }
        #pragma unroll 3
        for (int k = 0; k < KDIM; ++k) {
            const float* hb = hxw + k * 8;
            ull h0 = *(const ull*)(hb);
            ull h1 = *(const ull*)(hb + 2);
            ull h2 = *(const ull*)(hb + 4);
            ull h3 = *(const ull*)(hb + 6);
            float4 wa = *(const float4*)(wl + (k << 8));
            float4 wb = *(const float4*)(wl + (k << 8) + 4);
            float w[7] = {wa.x, wa.y, wa.z, wa.w, wb.x, wb.y, wb.z};
            #pragma unroll
            for (int j = 0; j < 7; ++j) {
                ull w2 = dup2(w[j]);
                fma2(acc[0][j], h0, w2);
                fma2(acc[1][j], h1, w2);
                fma2(acc[2][j], h2, w2);
                fma2(acc[3][j], h3, w2);
            }
        }
        // spill gates to warp-private smem (stride 9 -> conflict-free)
        #pragma unroll
        for (int j = 0; j < 7; ++j) {
            int c = lane * 7 + j;
            if (c < GATE) {
                float* gp = gw + c * GW_STR;
                #pragma unroll
                for (int p = 0; p < 4; ++p) {
                    float2 v = unpk(acc[p][j]);
                    gp[2 * p] = v.x; gp[2 * p + 1] = v.y;
                }
            }
        }
        __syncwarp();   // gate stores & hx reads done

        // x(t+1) into hx rows 0..6
        hxw[xk0 * 8 + xr0] = xv0;
        if (i1ok) hxw[xk1 * 8 + xr1] = xv1;

        // activation: 50 units x 8 rows, c in regs, h -> hx (MUFU.TANH)
        #pragma unroll
        for (int i = 0; i < 13; ++i) {
            int idx = lane + 32 * i;
            if (idx < HID * 8) {
                int u = idx >> 3, r = idx & 7;
                float gi = gw[u * GW_STR + r];
                float gf = gw[(HID + u) * GW_STR + r];
                float gg = gw[(2 * HID + u) * GW_STR + r];
                float go = gw[(3 * HID + u) * GW_STR + r];
                float c = sig_a(gf) * creg[i] + sig_a(gi) * tanh_a(gg);
                creg[i] = c;
                hxw[(7 + u) * 8 + r] = sig_a(go) * tanh_a(c);
            }
        }
        __syncwarp();   // h/x visible before next GEMM
    }

    // final h -> global [u][b]
    #pragma unroll
    for (int i = 0; i < 13; ++i) {
        int idx = lane + 32 * i;
        if (idx < HID * 8) {
            int u = idx >> 3, r = idx & 7;
            g_hT[u * B_SIZE + b0 + r] = hxw[(7 + u) * 8 + r];
        }
    }
}

// ---------------------------------------------------------------------------
// MLP: 512 threads (16 warps x 4 rows = 64 rows/block, grid 128);
// 4 warps/SMSP hides LDS->FMA chains. acc[2][CP] (no spills).
// ---------------------------------------------------------------------------
template<int IN, int OUT, int LA, int CP>
__device__ __forceinline__ void mlp_layer(const float* __restrict__ Wsh,
                                          const float* __restrict__ Bsh,
                                          const float* __restrict__ Xsh,
                                          float* __restrict__ Ysh,
                                          int lane, int rb)
{
    ull acc[2][CP];
    const bool act = lane < LA;
    #pragma unroll
    for (int j = 0; j < CP; ++j) {
        ull bv = dup2(act ? Bsh[j * LA + lane] : 0.f);
        acc[0][j] = bv; acc[1][j] = bv;
    }
    #pragma unroll 2
    for (int k = 0; k < IN; ++k) {
        const float* xr = &Xsh[k * RSTRM + rb];
        ull h0 = *(const ull*)(xr);
        ull h1 = *(const ull*)(xr + 2);
        #pragma unroll
        for (int j = 0; j < CP; ++j) {
            ull w2 = dup2(act ? Wsh[k * OUT + j * LA + lane] : 0.f);
            fma2(acc[0][j], h0, w2);
            fma2(acc[1][j], h1, w2);
        }
    }
    if (act) {
        #pragma unroll
        for (int j = 0; j < CP; ++j) {
            int c = j * LA + lane;
            float* yp = &Ysh[c * RSTRM + rb];
            #pragma unroll
            for (int rp = 0; rp < 2; ++rp) {
                float2 v = unpk(acc[rp][j]);
                v.x = fmaxf(v.x, 0.f);
                v.y = fmaxf(v.y, 0.f);
                *(float2*)(yp + 2 * rp) = v;
            }
        }
    }
}

// 16B-aligned smem layout (all offsets multiples of 4 floats)
#define OFF_W1 0
#define OFF_B1 8400
#define OFF_W2 8552            // 8400 + 152
#define OFF_B2 23552           // + 15000
#define OFF_W3 23656           // + 104
#define OFF_B3 33656           // + 10000
#define OFF_W4 33760           // + 104
#define OFF_B4 33864           // + 104
#define OFF_X  33868           // + 4
#define OFF_Y  (OFF_X + 150 * RSTRM)
#define MLP_SM_FLOATS (OFF_Y + 150 * RSTRM)
#define MLP_SM_BYTES  (MLP_SM_FLOATS * 4)

__global__ __launch_bounds__(TMLP, 1) void mlp_kernel(
    const float* __restrict__ state,
    const float* __restrict__ w1, const float* __restrict__ b1,
    const float* __restrict__ w2, const float* __restrict__ b2,
    const float* __restrict__ w3, const float* __restrict__ b3,
    const float* __restrict__ w4, const float* __restrict__ b4,
    float* __restrict__ out)
{
    extern __shared__ float sm[];
    float* w1s = sm + OFF_W1;
    float* b1s = sm + OFF_B1;
    float* w2s = sm + OFF_W2;
    float* b2s = sm + OFF_B2;
    float* w3s = sm + OFF_W3;
    float* b3s = sm + OFF_B3;
    float* w4s = sm + OFF_W4;
    float* b4s = sm + OFF_B4;
    float* X   = sm + OFF_X;
    float* Y   = sm + OFF_Y;

    const int tid = threadIdx.x;
    const int b0  = blockIdx.x * RPBM;

    // vectorized weight loads (all dst offsets 16B-aligned)
    for (int i = tid; i < 2100; i += TMLP)
        ((float4*)w1s)[i] = ((const float4*)w1)[i];
    for (int i = tid; i < 3750; i += TMLP)
        ((float4*)w2s)[i] = ((const float4*)w2)[i];
    for (int i = tid; i < 2500; i += TMLP)
        ((float4*)w3s)[i] = ((const float4*)w3)[i];
    if (tid < 150) b1s[tid] = b1[tid];
    if (tid < 100) { b2s[tid] = b2[tid]; b3s[tid] = b3[tid]; w4s[tid] = w4[tid]; }
    if (tid == 0) b4s[0] = b4[0];
    // joint = [self6 | h]
    for (int idx = tid; idx < 56 * RPBM; idx += TMLP) {
        int r = idx & 63, k = idx >> 6;
        X[k * RSTRM + r] = (k < 6) ? state[(size_t)(b0 + r) * ROWB + k]
                                   : g_hT[(k - 6) * B_SIZE + b0 + r];
    }
    __syncthreads();

    const int lane = tid & 31;
    const int rb   = (tid >> 5) * 4;    // 16 warps * 4 rows = 64 rows

    mlp_layer<56, 150, 30, 5>(w1s, b1s, X, Y, lane, rb);
    __syncthreads();
    mlp_layer<150, 100, 25, 4>(w2s, b2s, Y, X, lane, rb);
    __syncthreads();
    mlp_layer<100, 100, 25, 4>(w3s, b3s, X, Y, lane, rb);
    __syncthreads();

    if (tid < RPBM) {
        float a0 = 0.f, a1 = 0.f, a2 = 0.f, a3 = 0.f;
        #pragma unroll 5
        for (int k = 0; k < 100; k += 4) {
            a0 += Y[k * RSTRM + tid]       * w4s[k];
            a1 += Y[(k + 1) * RSTRM + tid] * w4s[k + 1];
            a2 += Y[(k + 2) * RSTRM + tid] * w4s[k + 2];
            a3 += Y[(k + 3) * RSTRM + tid] * w4s[k + 3];
        }
        out[b0 + tid] = a0 + a1 + a2 + a3 + b4s[0];
    }
}

// ---------------------------------------------------------------------------
extern "C" void kernel_launch(void* const* d_in, const int* in_sizes, int n_in,
                              void* d_out, int out_size)
{
    (void)in_sizes; (void)n_in; (void)out_size;
    const float* state = (const float*)d_in[0];
    const float* wih   = (const float*)d_in[11];
    const float* whh   = (const float*)d_in[12];
    const float* bih   = (const float*)d_in[13];
    const float* bhh   = (const float*)d_in[14];
    const float* w1    = (const float*)d_in[15];
    const float* b1    = (const float*)d_in[16];
    const float* w2    = (const float*)d_in[17];
    const float* b2    = (const float*)d_in[18];
    const float* w3    = (const float*)d_in[19];
    const float* b3    = (const float*)d_in[20];
    const float* w4    = (const float*)d_in[21];
    const float* b4    = (const float*)d_in[22];
    float* out = (float*)d_out;

    cudaFuncSetAttribute(lstm_kernel, cudaFuncAttributeMaxDynamicSharedMemorySize, LSTM_SM_BYTES);
    cudaFuncSetAttribute(mlp_kernel,  cudaFuncAttributeMaxDynamicSharedMemorySize, MLP_SM_BYTES);

    lstm_kernel<<<B_SIZE / 64, THREADS, LSTM_SM_BYTES>>>(state, wih, whh, bih, bhh);
    mlp_kernel<<<B_SIZE / RPBM, TMLP, MLP_SM_BYTES>>>(state, w1, b1, w2, b2,
                                                      w3, b3, w4, b4, out);
}